// round 15
// baseline (speedup 1.0000x reference)
#include <cuda_runtime.h>
#include <cstdint>

// ============================================================================
// DynamicConv1D: T=2048, B=16, C=512, H=8, R=64, K=7
//  phase 0: prep — split W (512x56, padded to n=64) into tf32 hi/lo MMA
//                  fragments, stored fragment-ordered in g_Bfrag.
//  phase 1: gemm — logits = query @ W via mma.m16n8k8 tf32 (3-term split =
//                  fp32-accurate). Head j == n8 tile j. Softmax fused in
//                  epilogue via quad shuffles.            [R8 verbatim]
//  phase 2: conv — out[t,b,h*64+r] = sum_kk w * xs[tl*512 + h*448 + r*7 + kk]
//                  staging now via cp.async (kills LDG->STS latency chain).
// ============================================================================

#define T_DIM 2048
#define B_DIM 16
#define C_DIM 512
#define H_DIM 8
#define K_DIM 7

// softmaxed weights: [row(=t*16+b)][head*8 + slot]  (slot 0..6 used)
__device__ float g_weights[(size_t)T_DIM * B_DIM * 64];
// B fragments: [kstep 0..63][j 0..7][lane 0..31] = (b0h, b1h, b0l, b1l)
__device__ float4 g_Bfrag[64 * 8 * 32];

// ---------------------------------------------------------------------------
__device__ __forceinline__ float tf32_rna(float v) {
    unsigned int u;
    asm("cvt.rna.tf32.f32 %0, %1;" : "=r"(u) : "f"(v));
    return __uint_as_float(u);
}

__device__ __forceinline__ void mma_tf32(float* d, const unsigned int* a,
                                         unsigned int b0, unsigned int b1) {
    asm volatile(
        "mma.sync.aligned.m16n8k8.row.col.f32.tf32.tf32.f32 "
        "{%0,%1,%2,%3}, {%4,%5,%6,%7}, {%8,%9}, {%0,%1,%2,%3};"
        : "+f"(d[0]), "+f"(d[1]), "+f"(d[2]), "+f"(d[3])
        : "r"(a[0]), "r"(a[1]), "r"(a[2]), "r"(a[3]), "r"(b0), "r"(b1));
}

__device__ __forceinline__ void cp16(void* smem_dst, const void* gmem_src) {
    unsigned int d = (unsigned int)__cvta_generic_to_shared(smem_dst);
    asm volatile("cp.async.ca.shared.global [%0], [%1], 16;" :: "r"(d), "l"(gmem_src));
}

// ---------------------------------------------------------------------------
// Kernel 0: build tf32 hi/lo B fragments. idx = (ks*8 + j)*32 + lane.
// ---------------------------------------------------------------------------
__global__ void prep_b_kernel(const float* __restrict__ W) {
    int idx  = blockIdx.x * 256 + threadIdx.x;      // 0..16383
    int lane = idx & 31;
    int j    = (idx >> 5) & 7;
    int ks   = idx >> 8;
    int tg   = lane & 3;
    int g    = lane >> 2;
    int k0   = ks * 8 + tg;
    float b0 = (g < 7) ? W[k0 * 56 + j * 7 + g] : 0.0f;
    float b1 = (g < 7) ? W[(k0 + 4) * 56 + j * 7 + g] : 0.0f;
    float b0h = tf32_rna(b0), b0l = tf32_rna(b0 - b0h);
    float b1h = tf32_rna(b1), b1l = tf32_rna(b1 - b1h);
    g_Bfrag[idx] = make_float4(b0h, b1h, b0l, b1l);
}

// ---------------------------------------------------------------------------
// Kernel 1: GEMM M=32768 N=64 K=512 + fused softmax.  [R8 verbatim]
// 256 threads = 8 warps; warp w owns ONE m16 tile (rows w*16..w*16+15) x n64.
// BK=32 (4 k-steps of 8), cp.async double-buffered A (row-major stride 36:
// A-frag LDS.32 banks = 4g+tg, conflict-free) and B (fragment-ordered copy).
// ---------------------------------------------------------------------------
#define AS_STRIDE 36
#define AS_WORDS  (128 * AS_STRIDE)                 // 4608 words
#define BS_ELEMS  (4 * 8 * 32)                      // float4 per tile = 1024
#define GEMM_SMEM (2 * AS_WORDS * 4 + 2 * BS_ELEMS * 16)   // 69632 B

__global__ __launch_bounds__(256, 2)
void gemm_softmax_kernel(const float* __restrict__ query) {
    extern __shared__ float smem[];
    float*  As[2] = { smem, smem + AS_WORDS };
    float4* Bs[2] = { (float4*)(smem + 2 * AS_WORDS),
                      (float4*)(smem + 2 * AS_WORDS) + BS_ELEMS };

    const int tid  = threadIdx.x;
    const int wrp  = tid >> 5;
    const int lane = tid & 31;
    const int g    = lane >> 2;
    const int tg   = lane & 3;
    const int blockRow = blockIdx.x * 128;

    float d[8][4];
    #pragma unroll
    for (int j = 0; j < 8; j++)
        #pragma unroll
        for (int q = 0; q < 4; q++) d[j][q] = 0.0f;

    #define STAGE(t, buf)                                                     \
    {                                                                         \
        int k0 = (t) * 32;                                                    \
        _Pragma("unroll")                                                     \
        for (int i = 0; i < 4; i++) {                                         \
            int linear = tid + i * 256;             /* 0..1023 */             \
            int row    = linear >> 3;                                         \
            int f4     = linear & 7;                                          \
            cp16(&As[buf][row * AS_STRIDE + f4 * 4],                          \
                 query + (size_t)(blockRow + row) * C_DIM + k0 + f4 * 4);     \
        }                                                                     \
        const float4* src = g_Bfrag + (size_t)(t) * BS_ELEMS;                 \
        _Pragma("unroll")                                                     \
        for (int i = 0; i < 4; i++) {                                         \
            int linear = tid + i * 256;                                       \
            cp16(&Bs[buf][linear], src + linear);                             \
        }                                                                     \
        asm volatile("cp.async.commit_group;");                               \
    }

    STAGE(0, 0);
    STAGE(1, 1);

    for (int t = 0; t < 16; t++) {
        if (t < 15) asm volatile("cp.async.wait_group 1;");
        else        asm volatile("cp.async.wait_group 0;");
        __syncthreads();
        const int buf = t & 1;
        const float*  a_ = As[buf];
        const float4* b_ = Bs[buf];

        #pragma unroll
        for (int ks = 0; ks < 4; ks++) {
            // ---- A fragment + tf32 split, one m16 tile ----
            const int rbase = wrp * 16;
            const int col   = ks * 8 + tg;
            float a0 = a_[(rbase + g)     * AS_STRIDE + col];
            float a1 = a_[(rbase + g + 8) * AS_STRIDE + col];
            float a2 = a_[(rbase + g)     * AS_STRIDE + col + 4];
            float a3 = a_[(rbase + g + 8) * AS_STRIDE + col + 4];
            float h0 = tf32_rna(a0), h1 = tf32_rna(a1);
            float h2 = tf32_rna(a2), h3 = tf32_rna(a3);
            unsigned int ah[4], al[4];
            ah[0] = __float_as_uint(h0); al[0] = __float_as_uint(tf32_rna(a0 - h0));
            ah[1] = __float_as_uint(h1); al[1] = __float_as_uint(tf32_rna(a1 - h1));
            ah[2] = __float_as_uint(h2); al[2] = __float_as_uint(tf32_rna(a2 - h2));
            ah[3] = __float_as_uint(h3); al[3] = __float_as_uint(tf32_rna(a3 - h3));
            #pragma unroll
            for (int j = 0; j < 8; j++) {
                float4 bv = b_[(ks * 8 + j) * 32 + lane];
                unsigned int b0h = __float_as_uint(bv.x), b1h = __float_as_uint(bv.y);
                unsigned int b0l = __float_as_uint(bv.z), b1l = __float_as_uint(bv.w);
                mma_tf32(d[j], ah, b0h, b1h);   // hi*hi
                mma_tf32(d[j], al, b0h, b1h);   // lo*hi
                mma_tf32(d[j], ah, b0l, b1l);   // hi*lo
            }
        }
        __syncthreads();
        if (t + 2 < 16) STAGE(t + 2, buf);
    }

    // ---- epilogue: softmax per (row, head) across the tg-quad, store ----
    #pragma unroll
    for (int rh = 0; rh < 2; rh++) {
        int row = blockRow + wrp * 16 + g + rh * 8;
        float* wrow = g_weights + (size_t)row * 64;
        #pragma unroll
        for (int j = 0; j < 8; j++) {
            float c0 = d[j][rh * 2 + 0];
            float c1 = d[j][rh * 2 + 1];
            bool pad = (tg == 3);
            float m = pad ? c0 : fmaxf(c0, c1);
            m = fmaxf(m, __shfl_xor_sync(0xffffffffu, m, 1));
            m = fmaxf(m, __shfl_xor_sync(0xffffffffu, m, 2));
            float e0 = __expf(c0 - m);
            float e1 = pad ? 0.0f : __expf(c1 - m);
            float s = e0 + e1;
            s += __shfl_xor_sync(0xffffffffu, s, 1);
            s += __shfl_xor_sync(0xffffffffu, s, 2);
            float inv = 1.0f / s;
            *(float2*)&wrow[j * 8 + 2 * tg] = make_float2(e0 * inv, e1 * inv);
        }
    }
}

// ---------------------------------------------------------------------------
// Kernel 2: gathered conv. Block = (t-tile of 16, one b), 512 threads, 48 KB
// smem, 3 blocks/SM. Staging via cp.async: no LDG->STS register roundtrip,
// long-latency fill handled by the DMA path while warps run to the barrier.
// Taps are 7 consecutive smem floats, lane stride 7 -> conflict-free.
// ---------------------------------------------------------------------------
#define TT 16
#define XS_ROWS (TT + K_DIM - 1)            // 22
#define SMEM_CONV ((XS_ROWS * C_DIM + TT * 64) * 4)   // 49152 bytes

__global__ __launch_bounds__(512, 3)
void conv_kernel(const float* __restrict__ x, float* __restrict__ out) {
    extern __shared__ float smem[];
    float* xs = smem;                        // 22*512
    float* ws = smem + XS_ROWS * C_DIM;      // 16*64

    const int tid = threadIdx.x;
    const int t0  = (blockIdx.x >> 4) * TT;
    const int b   = blockIdx.x & 15;

    // ---- stage weights via cp.async: 256 x 16B chunks ----
    if (tid < TT * 16) {
        int tl = tid >> 4;                   // 0..15
        int f4 = tid & 15;                   // 0..15
        cp16(&ws[tl * 64 + f4 * 4],
             g_weights + ((size_t)(t0 + tl) * B_DIM + b) * 64 + f4 * 4);
    }
    // ---- stage x tile via cp.async (2816 x 16B chunks); edges zero via STS --
    #pragma unroll
    for (int i = 0; i < 6; i++) {
        int linear = tid + i * 512;          // 0..3071; guard < 2816
        if (linear < XS_ROWS * (C_DIM / 4)) {
            int irow = linear >> 7;          // 0..21
            int c4   = linear & 127;
            int tg   = t0 - 3 + irow;
            if (tg >= 0 && tg < T_DIM) {
                cp16(&xs[irow * C_DIM + c4 * 4],
                     x + ((size_t)tg * B_DIM + b) * C_DIM + c4 * 4);
            } else {
                *(float4*)&xs[irow * C_DIM + c4 * 4] = make_float4(0.f, 0.f, 0.f, 0.f);
            }
        }
    }
    asm volatile("cp.async.commit_group;");
    asm volatile("cp.async.wait_group 0;");
    __syncthreads();

    const int c  = tid;
    const int h  = c >> 6;                   // uniform per warp
    const int fb = h * 448 + (c & 63) * 7;   // flat offset of first tap

    #pragma unroll 4
    for (int tl = 0; tl < TT; tl++) {
        const float4* wp = (const float4*)&ws[tl * 64 + h * 8];   // broadcast
        float4 w0 = wp[0];
        float4 w1 = wp[1];
        const float* xp = &xs[tl * C_DIM + fb];   // 7 consecutive floats
        float p01 = w0.x * xp[0];
        p01 = fmaf(w0.y, xp[1], p01);
        float p23 = w0.z * xp[2];
        p23 = fmaf(w0.w, xp[3], p23);
        float p45 = w1.x * xp[4];
        p45 = fmaf(w1.y, xp[5], p45);
        float p6  = w1.z * xp[6];
        float acc = (p01 + p23) + (p45 + p6);
        out[((size_t)(t0 + tl) * B_DIM + b) * C_DIM + c] = acc;
    }
}

// ---------------------------------------------------------------------------
extern "C" void kernel_launch(void* const* d_in, const int* in_sizes, int n_in,
                              void* d_out, int out_size) {
    const float* x     = (const float*)d_in[0];
    const float* query = (const float*)d_in[1];
    const float* W     = (const float*)d_in[2];
    float* out         = (float*)d_out;

    cudaFuncSetAttribute(gemm_softmax_kernel, cudaFuncAttributeMaxDynamicSharedMemorySize, GEMM_SMEM);
    cudaFuncSetAttribute(conv_kernel, cudaFuncAttributeMaxDynamicSharedMemorySize, SMEM_CONV);

    // phase 0: 16384 fragment entries / 256
    prep_b_kernel<<<64, 256>>>(W);
    // phase 1: 32768 rows / 128 = 256 blocks x 256 threads
    gemm_softmax_kernel<<<256, 256, GEMM_SMEM>>>(query);
    // phase 2: 128 t-tiles x 16 batches
    conv_kernel<<<(T_DIM / TT) * B_DIM, 512, SMEM_CONV>>>(x, out);
}

// round 16
// speedup vs baseline: 1.2153x; 1.2153x over previous
#include <cuda_runtime.h>
#include <cstdint>

// ============================================================================
// DynamicConv1D: T=2048, B=16, C=512, H=8, R=64, K=7
//  phase 0: prep — split W (512x56, padded to n=64) into tf32 hi/lo MMA
//                  fragments, stored fragment-ordered in g_Bfrag.
//  phase 1: gemm — logits = query @ W via mma.m16n8k8 tf32 (3-term split =
//                  fp32-accurate). Head j == n8 tile j. Softmax fused in
//                  epilogue via quad shuffles. R8 instruction stream; B now
//                  read via __ldg (L1 broadcast) -> smem halves, 3 blocks/SM.
//  phase 2: conv — out[t,b,h*64+r] = sum_kk w * xs[tl*512 + h*448 + r*7 + kk]
//                  [R8 verbatim, 43.8 us]
// ============================================================================

#define T_DIM 2048
#define B_DIM 16
#define C_DIM 512
#define H_DIM 8
#define K_DIM 7

// softmaxed weights: [row(=t*16+b)][head*8 + slot]  (slot 0..6 used)
__device__ float g_weights[(size_t)T_DIM * B_DIM * 64];
// B fragments: [kstep 0..63][j 0..7][lane 0..31] = (b0h, b1h, b0l, b1l)
__device__ float4 g_Bfrag[64 * 8 * 32];

// ---------------------------------------------------------------------------
__device__ __forceinline__ float tf32_rna(float v) {
    unsigned int u;
    asm("cvt.rna.tf32.f32 %0, %1;" : "=r"(u) : "f"(v));
    return __uint_as_float(u);
}

__device__ __forceinline__ void mma_tf32(float* d, const unsigned int* a,
                                         unsigned int b0, unsigned int b1) {
    asm volatile(
        "mma.sync.aligned.m16n8k8.row.col.f32.tf32.tf32.f32 "
        "{%0,%1,%2,%3}, {%4,%5,%6,%7}, {%8,%9}, {%0,%1,%2,%3};"
        : "+f"(d[0]), "+f"(d[1]), "+f"(d[2]), "+f"(d[3])
        : "r"(a[0]), "r"(a[1]), "r"(a[2]), "r"(a[3]), "r"(b0), "r"(b1));
}

__device__ __forceinline__ void cp16(void* smem_dst, const void* gmem_src) {
    unsigned int d = (unsigned int)__cvta_generic_to_shared(smem_dst);
    asm volatile("cp.async.ca.shared.global [%0], [%1], 16;" :: "r"(d), "l"(gmem_src));
}

// ---------------------------------------------------------------------------
// Kernel 0: build tf32 hi/lo B fragments. idx = (ks*8 + j)*32 + lane.
// ---------------------------------------------------------------------------
__global__ void prep_b_kernel(const float* __restrict__ W) {
    int idx  = blockIdx.x * 256 + threadIdx.x;      // 0..16383
    int lane = idx & 31;
    int j    = (idx >> 5) & 7;
    int ks   = idx >> 8;
    int tg   = lane & 3;
    int g    = lane >> 2;
    int k0   = ks * 8 + tg;
    float b0 = (g < 7) ? W[k0 * 56 + j * 7 + g] : 0.0f;
    float b1 = (g < 7) ? W[(k0 + 4) * 56 + j * 7 + g] : 0.0f;
    float b0h = tf32_rna(b0), b0l = tf32_rna(b0 - b0h);
    float b1h = tf32_rna(b1), b1l = tf32_rna(b1 - b1h);
    g_Bfrag[idx] = make_float4(b0h, b1h, b0l, b1l);
}

// ---------------------------------------------------------------------------
// Kernel 1: GEMM M=32768 N=64 K=512 + fused softmax.
// 256 threads = 8 warps; warp w owns ONE m16 tile (rows w*16..w*16+15) x n64.
// BK=32 (4 k-steps of 8), cp.async double-buffered A ONLY (row-major stride
// 36: A-frag LDS.32 banks = 4g+tg, conflict-free). B fragments read straight
// from g_Bfrag via __ldg: all warps/blocks issue identical addresses ->
// L1-broadcast hits (~L1 lat ~= LDS lat), L2-resident 256 KB working set.
// smem = 36.9 KB -> 3 blocks/SM (reg cap 85 via launch_bounds).
// ---------------------------------------------------------------------------
#define AS_STRIDE 36
#define AS_WORDS  (128 * AS_STRIDE)                 // 4608 words
#define BS_ELEMS  (4 * 8 * 32)                      // float4 per k-tile = 1024
#define GEMM_SMEM (2 * AS_WORDS * 4)                // 36864 B

__global__ __launch_bounds__(256, 3)
void gemm_softmax_kernel(const float* __restrict__ query) {
    extern __shared__ float smem[];
    float* As[2] = { smem, smem + AS_WORDS };

    const int tid  = threadIdx.x;
    const int wrp  = tid >> 5;
    const int lane = tid & 31;
    const int g    = lane >> 2;
    const int tg   = lane & 3;
    const int blockRow = blockIdx.x * 128;

    float d[8][4];
    #pragma unroll
    for (int j = 0; j < 8; j++)
        #pragma unroll
        for (int q = 0; q < 4; q++) d[j][q] = 0.0f;

    #define STAGE(t, buf)                                                     \
    {                                                                         \
        int k0 = (t) * 32;                                                    \
        _Pragma("unroll")                                                     \
        for (int i = 0; i < 4; i++) {                                         \
            int linear = tid + i * 256;             /* 0..1023 */             \
            int row    = linear >> 3;                                         \
            int f4     = linear & 7;                                          \
            cp16(&As[buf][row * AS_STRIDE + f4 * 4],                          \
                 query + (size_t)(blockRow + row) * C_DIM + k0 + f4 * 4);     \
        }                                                                     \
        asm volatile("cp.async.commit_group;");                               \
    }

    STAGE(0, 0);
    STAGE(1, 1);

    for (int t = 0; t < 16; t++) {
        if (t < 15) asm volatile("cp.async.wait_group 1;");
        else        asm volatile("cp.async.wait_group 0;");
        __syncthreads();
        const int buf = t & 1;
        const float*  a_ = As[buf];
        const float4* b_ = g_Bfrag + (size_t)t * BS_ELEMS;   // L1/L2 path

        #pragma unroll
        for (int ks = 0; ks < 4; ks++) {
            // ---- A fragment + tf32 split, one m16 tile ----
            const int rbase = wrp * 16;
            const int col   = ks * 8 + tg;
            float a0 = a_[(rbase + g)     * AS_STRIDE + col];
            float a1 = a_[(rbase + g + 8) * AS_STRIDE + col];
            float a2 = a_[(rbase + g)     * AS_STRIDE + col + 4];
            float a3 = a_[(rbase + g + 8) * AS_STRIDE + col + 4];
            float h0 = tf32_rna(a0), h1 = tf32_rna(a1);
            float h2 = tf32_rna(a2), h3 = tf32_rna(a3);
            unsigned int ah[4], al[4];
            ah[0] = __float_as_uint(h0); al[0] = __float_as_uint(tf32_rna(a0 - h0));
            ah[1] = __float_as_uint(h1); al[1] = __float_as_uint(tf32_rna(a1 - h1));
            ah[2] = __float_as_uint(h2); al[2] = __float_as_uint(tf32_rna(a2 - h2));
            ah[3] = __float_as_uint(h3); al[3] = __float_as_uint(tf32_rna(a3 - h3));
            #pragma unroll
            for (int j = 0; j < 8; j++) {
                float4 bv = __ldg(&b_[(ks * 8 + j) * 32 + lane]);
                unsigned int b0h = __float_as_uint(bv.x), b1h = __float_as_uint(bv.y);
                unsigned int b0l = __float_as_uint(bv.z), b1l = __float_as_uint(bv.w);
                mma_tf32(d[j], ah, b0h, b1h);   // hi*hi
                mma_tf32(d[j], al, b0h, b1h);   // lo*hi
                mma_tf32(d[j], ah, b0l, b1l);   // hi*lo
            }
        }
        __syncthreads();
        if (t + 2 < 16) STAGE(t + 2, buf);
    }

    // ---- epilogue: softmax per (row, head) across the tg-quad, store ----
    // lane holds cols {2tg, 2tg+1}; tap 7 (tg==3, second col) is the N-pad:
    // excluded from max/sum, stored as 0.
    #pragma unroll
    for (int rh = 0; rh < 2; rh++) {
        int row = blockRow + wrp * 16 + g + rh * 8;
        float* wrow = g_weights + (size_t)row * 64;
        #pragma unroll
        for (int j = 0; j < 8; j++) {
            float c0 = d[j][rh * 2 + 0];
            float c1 = d[j][rh * 2 + 1];
            bool pad = (tg == 3);
            float m = pad ? c0 : fmaxf(c0, c1);
            m = fmaxf(m, __shfl_xor_sync(0xffffffffu, m, 1));
            m = fmaxf(m, __shfl_xor_sync(0xffffffffu, m, 2));
            float e0 = __expf(c0 - m);
            float e1 = pad ? 0.0f : __expf(c1 - m);
            float s = e0 + e1;
            s += __shfl_xor_sync(0xffffffffu, s, 1);
            s += __shfl_xor_sync(0xffffffffu, s, 2);
            float inv = 1.0f / s;
            *(float2*)&wrow[j * 8 + 2 * tg] = make_float2(e0 * inv, e1 * inv);
        }
    }
}

// ---------------------------------------------------------------------------
// Kernel 2: gathered conv (known-good R8 config, 43.8 us). Block = (t-tile of
// 16, one b), 512 threads, 48 KB smem, 3 blocks/SM. Taps are 7 consecutive
// smem floats, lane stride 7 words -> conflict-free (gcd(7,32)=1). Tree accum.
// ---------------------------------------------------------------------------
#define TT 16
#define XS_ROWS (TT + K_DIM - 1)            // 22
#define SMEM_CONV ((XS_ROWS * C_DIM + TT * 64) * 4)   // 49152 bytes

__global__ __launch_bounds__(512, 3)
void conv_kernel(const float* __restrict__ x, float* __restrict__ out) {
    extern __shared__ float smem[];
    float* xs = smem;                        // 22*512
    float* ws = smem + XS_ROWS * C_DIM;      // 16*64

    const int tid = threadIdx.x;
    const int t0  = (blockIdx.x >> 4) * TT;
    const int b   = blockIdx.x & 15;

    if (tid < TT * 16) {
        int tl = tid >> 4;                   // 0..15
        int f4 = tid & 15;                   // 0..15
        const float4* src = (const float4*)(g_weights + ((size_t)(t0 + tl) * B_DIM + b) * 64);
        *(float4*)&ws[tl * 64 + f4 * 4] = src[f4];
    }
    for (int linear = tid; linear < XS_ROWS * (C_DIM / 4); linear += 512) {
        int irow = linear >> 7;              // 0..21
        int c4   = linear & 127;
        int tg   = t0 - 3 + irow;
        float4 v = make_float4(0.0f, 0.0f, 0.0f, 0.0f);
        if (tg >= 0 && tg < T_DIM)
            v = *(const float4*)(x + ((size_t)tg * B_DIM + b) * C_DIM + c4 * 4);
        *(float4*)&xs[irow * C_DIM + c4 * 4] = v;
    }
    __syncthreads();

    const int c  = tid;
    const int h  = c >> 6;                   // uniform per warp
    const int fb = h * 448 + (c & 63) * 7;   // flat offset of first tap

    #pragma unroll 4
    for (int tl = 0; tl < TT; tl++) {
        const float4* wp = (const float4*)&ws[tl * 64 + h * 8];   // broadcast
        float4 w0 = wp[0];
        float4 w1 = wp[1];
        const float* xp = &xs[tl * C_DIM + fb];   // 7 consecutive floats
        float p01 = w0.x * xp[0];
        p01 = fmaf(w0.y, xp[1], p01);
        float p23 = w0.z * xp[2];
        p23 = fmaf(w0.w, xp[3], p23);
        float p45 = w1.x * xp[4];
        p45 = fmaf(w1.y, xp[5], p45);
        float p6  = w1.z * xp[6];
        float acc = (p01 + p23) + (p45 + p6);
        out[((size_t)(t0 + tl) * B_DIM + b) * C_DIM + c] = acc;
    }
}

// ---------------------------------------------------------------------------
extern "C" void kernel_launch(void* const* d_in, const int* in_sizes, int n_in,
                              void* d_out, int out_size) {
    const float* x     = (const float*)d_in[0];
    const float* query = (const float*)d_in[1];
    const float* W     = (const float*)d_in[2];
    float* out         = (float*)d_out;

    cudaFuncSetAttribute(gemm_softmax_kernel, cudaFuncAttributeMaxDynamicSharedMemorySize, GEMM_SMEM);
    cudaFuncSetAttribute(conv_kernel, cudaFuncAttributeMaxDynamicSharedMemorySize, SMEM_CONV);

    // phase 0: 16384 fragment entries / 256
    prep_b_kernel<<<64, 256>>>(W);
    // phase 1: 32768 rows / 128 = 256 blocks x 256 threads
    gemm_softmax_kernel<<<256, 256, GEMM_SMEM>>>(query);
    // phase 2: 128 t-tiles x 16 batches
    conv_kernel<<<(T_DIM / TT) * B_DIM, 512, SMEM_CONV>>>(x, out);
}